// round 14
// baseline (speedup 1.0000x reference)
#include <cuda_runtime.h>
#include <cstdint>
#include <math.h>

#define D_DIM   1024
#define T_DIM   50
#define STRIDEQ 10
#define NUM_POS 16
#define MAX_B   4096
#define MAX_KP  13108   /* ceil(131072/10) */
#define NWMAX   416     /* ceil(13108/32)=410, padded */

typedef unsigned long long ull;

// ---- device scratch (static; no allocations allowed) ----
__device__ ulonglong2 g_q[MAX_KP];
__device__ ulonglong2 g_a[MAX_B];
__device__ int        g_sel[MAX_B * NUM_POS];
__device__ int        g_cnt[MAX_B];
__device__ int        g_ready[MAX_B];
__device__ float      g_per[MAX_B];
__device__ unsigned   g_counter;

// ------------------------------------------------------------------
// Kernel 1: pack labels (strided queue rows + anchors). Warp per row.
// Also resets g_ready and g_counter.
// ------------------------------------------------------------------
__global__ void prep_labels(const int* __restrict__ xlab,
                            const int* __restrict__ qlab,
                            int B, int Kp) {
    int gt = blockIdx.x * blockDim.x + threadIdx.x;
    if (gt == 0) g_counter = 0;
    if (gt < MAX_B) g_ready[gt] = 0;

    int warp = gt >> 5;
    int lane = threadIdx.x & 31;
    if (warp >= Kp + B) return;

    const int* lp = (warp < Kp)
        ? qlab + (long long)warp * STRIDEQ * (T_DIM * 2)
        : xlab + (long long)(warp - Kp) * (T_DIM * 2);

    int2 va = ((const int2*)lp)[lane];
    int l0b = 0, l1b = 0;
    if (32 + lane < T_DIM) {
        int2 vb = ((const int2*)lp)[32 + lane];
        l0b = vb.x; l1b = vb.y;
    }
    unsigned b0lo = __ballot_sync(0xffffffffu, va.x != 0);
    unsigned b1lo = __ballot_sync(0xffffffffu, va.y != 0);
    unsigned b0hi = __ballot_sync(0xffffffffu, l0b != 0);
    unsigned b1hi = __ballot_sync(0xffffffffu, l1b != 0);
    if (lane == 0) {
        ull v0 = (ull)b0lo | ((ull)b0hi << 32);
        ull v1 = (ull)b1lo | ((ull)b1hi << 32);
        if (warp < Kp) g_q[warp]      = make_ulonglong2(v0, v1);
        else           g_a[warp - Kp] = make_ulonglong2(v0, v1);
    }
}

// ------------------------------------------------------------------
// Shared-memory select (validated R10/R13 structure): full block runs
// it; results land in s_sel / *s_cnt. Threshold table is built with
// the SAME fp32 expression as the reference (bit-exact, validated).
// ------------------------------------------------------------------
__device__ void do_select(int b, int Kp, unsigned* s_words, int* s_T,
                          int* s_sel, int* s_cnt) {
    int tid  = threadIdx.x;
    int w    = tid >> 5;
    int lane = tid & 31;

    float c = 1.0f / (sqrtf(2.0f) + 1e-8f);
    if (tid < 64) {
        int nE = tid;
        int t;
        if ((float)nE >= 25.0f) t = 0;
        else {
            t = (int)((25.0f - (float)nE) / c) - 2;
            if (t < 0) t = 0;
            while ((float)nE + (float)t * c < 25.0f) t++;
        }
        s_T[tid] = t;
    }

    ulonglong2 av = g_a[b];
    ull a0 = av.x, a1 = av.y;
    ull da = a0 & a1, xa = a0 ^ a1, orA = a0 | a1;
    __syncthreads();

    int total    = 0;
    int scan_end = 0;
#pragma unroll 1
    for (int base = 0; base < Kp; base += 512) {
        int k = base + tid;
        bool pred = false;
        if (k < Kp) {
            ulonglong2 qv = g_q[k];
            ull mE = ~(qv.x ^ a0) & ~(qv.y ^ a1) & orA;
            ull mc = (da & (qv.x ^ qv.y)) | (xa & (qv.x & qv.y));
            pred = (__popcll(mc) >= s_T[__popcll(mE)]);
        }
        unsigned m = __ballot_sync(0xffffffffu, pred);
        if (lane == 0) s_words[(base >> 5) + w] = m;
        total += __syncthreads_count(pred);
        scan_end = (base + 512 < Kp) ? base + 512 : Kp;
        if (total >= NUM_POS) break;
    }

    if (w == 0) {
        int nwords = (scan_end + 31) >> 5;
        int run = 0;
        for (int g = 0; g * 32 < nwords && run < NUM_POS; g++) {
            int wi = g * 32 + lane;
            unsigned word = (wi < nwords) ? s_words[wi] : 0u;
            int my = __popc(word);
            int pre = my;
#pragma unroll
            for (int o = 1; o < 32; o <<= 1) {
                int v = __shfl_up_sync(0xffffffffu, pre, o);
                if (lane >= o) pre += v;
            }
            int gtot = __shfl_sync(0xffffffffu, pre, 31);
            int rank = run + pre - my;
            while (word && rank < NUM_POS) {
                int bit = __ffs(word) - 1;
                word &= word - 1;
                s_sel[rank++] = wi * 32 + bit;
            }
            run += gtot;
        }
        if (lane == 0) *s_cnt = (total < NUM_POS) ? total : NUM_POS;
    }
}

// ------------------------------------------------------------------
// Kernel 2 (mega): even blocks = select producer, odd = loss consumer.
// Consumer spin-waits with bounded fallback (deadlock-proof, value-
// identical). Select (ALU) and loss (L2) overlap on every SM.
// ------------------------------------------------------------------
__global__ void __launch_bounds__(512, 4)
mega_kernel(const float* __restrict__ xq, const float* __restrict__ qf,
            float* __restrict__ out, int B, int Kp) {
    __shared__ float4   s_anchor4[D_DIM / 4];
    __shared__ double   s_red[512];
    __shared__ unsigned s_words[NWMAX];
    __shared__ float    s_ssq[256];
    __shared__ int      s_T[64];
    __shared__ int      s_sel[NUM_POS];
    __shared__ float    s_loss[NUM_POS];
    __shared__ int      s_cnt;
    __shared__ int      s_ok;
    __shared__ int      s_last;

    int bid  = blockIdx.x;
    int b    = bid >> 1;
    int tid  = threadIdx.x;
    int w    = tid >> 5;
    int lane = tid & 31;

    if ((bid & 1) == 0) {
        // ---------------- producer: select ----------------
        do_select(b, Kp, s_words, s_T, s_sel, &s_cnt);
        __syncthreads();
        if (tid == 0) {
            int cnt = s_cnt;
#pragma unroll
            for (int i = 0; i < NUM_POS; i++)
                g_sel[b * NUM_POS + i] = (i < cnt) ? s_sel[i] : 0;
            g_cnt[b] = cnt;
            __threadfence();
            atomicExch(&g_ready[b], 1);
        }
        return;
    }

    // ---------------- consumer: loss ----------------
    // stage anchor row first (memory work overlaps producer's select)
    if (tid >= 256) {
        int i = tid - 256;
        float4 v = ((const float4*)(xq + (long long)b * D_DIM))[i];
        s_anchor4[i] = v;
        s_ssq[i] = v.x * v.x + v.y * v.y + v.z * v.z + v.w * v.w;
    }
    if (tid == 0) {
        int ok = 0;
        for (int it = 0; it < 40000; ++it) {
            if (atomicAdd(&g_ready[b], 0) != 0) { ok = 1; break; }
            __nanosleep(200);
        }
        if (ok) __threadfence();
        s_ok = ok;
    }
    __syncthreads();

    if (!s_ok) {
        // fallback: compute the identical selection ourselves
        do_select(b, Kp, s_words, s_T, s_sel, &s_cnt);
    } else {
        if (tid < NUM_POS) s_sel[tid] = g_sel[b * NUM_POS + tid];
        if (tid == 0)      s_cnt     = g_cnt[b];
    }
    __syncthreads();

    int cnt = s_cnt;
    float loss = 0.f;
    if (w < cnt) {
        int kp = s_sel[w];
        const float4* pk = (const float4*)(qf + (long long)kp * STRIDEQ * D_DIM);
        const float4* pa = (const float4*)s_anchor4;
        float dot = 0.f, kss = 0.f;
#pragma unroll
        for (int i = 0; i < D_DIM / 4 / 32; i++) {
            float4 a  = pa[lane + i * 32];
            float4 kk = pk[lane + i * 32];
            dot += a.x * kk.x + a.y * kk.y + a.z * kk.z + a.w * kk.w;
            kss += kk.x * kk.x + kk.y * kk.y + kk.z * kk.z + kk.w * kk.w;
        }
#pragma unroll
        for (int o = 16; o; o >>= 1) {
            dot += __shfl_xor_sync(0xffffffffu, dot, o);
            kss += __shfl_xor_sync(0xffffffffu, kss, o);
        }
        float qss = s_ssq[lane] + s_ssq[lane + 32] + s_ssq[lane + 64]
                  + s_ssq[lane + 96] + s_ssq[lane + 128] + s_ssq[lane + 160]
                  + s_ssq[lane + 192] + s_ssq[lane + 224];
#pragma unroll
        for (int o = 16; o; o >>= 1) qss += __shfl_xor_sync(0xffffffffu, qss, o);

        float inv_q = 1.0f / (sqrtf(qss) + 1e-8f);
        float inv_k = 1.0f / (sqrtf(kss) + 1e-8f);
        float s = dot * inv_q * inv_k * 2.0f;     // / TEMPERATURE(0.5)
        float z = -s;                              // -log_sigmoid(s)
        loss = fmaxf(z, 0.f) + log1pf(expf(-fabsf(z)));
    }
    if (lane == 0 && w < NUM_POS) s_loss[w] = loss;
    __syncthreads();

    if (tid == 0) {
        float sum = 0.f;
#pragma unroll
        for (int i = 0; i < NUM_POS; i++) sum += (i < cnt) ? s_loss[i] : 0.f;
        g_per[b] = (cnt > 0) ? (sum / (float)cnt) : 0.f;
        __threadfence();
        unsigned t = atomicAdd(&g_counter, 1u);
        s_last = (t == (unsigned)(B - 1)) ? 1 : 0;
    }
    __syncthreads();

    if (s_last) {
        double acc = 0.0;
        for (int i = tid; i < B; i += 512) acc += (double)g_per[i];
        s_red[tid] = acc;
        __syncthreads();
        for (int s = 256; s; s >>= 1) {
            if (tid < s) s_red[tid] += s_red[tid + s];
            __syncthreads();
        }
        if (tid == 0) out[0] = (float)(s_red[0] / (double)B);
    }
}

extern "C" void kernel_launch(void* const* d_in, const int* in_sizes, int n_in,
                              void* d_out, int out_size) {
    const float* xq   = (const float*)d_in[0];
    const int*   xlab = (const int*)  d_in[1];
    const float* qf   = (const float*)d_in[2];
    const int*   qlab = (const int*)  d_in[3];

    int B  = in_sizes[0] / D_DIM;                 // 4096
    int K  = in_sizes[2] / D_DIM;                 // 131072
    int Kp = (K + STRIDEQ - 1) / STRIDEQ;         // 13108

    int warps  = Kp + B;
    int blocks = (warps * 32 + 255) / 256;
    prep_labels<<<blocks, 256>>>(xlab, qlab, B, Kp);
    mega_kernel<<<2 * B, 512>>>(xq, qf, (float*)d_out, B, Kp);
}

// round 15
// speedup vs baseline: 1.5326x; 1.5326x over previous
#include <cuda_runtime.h>
#include <cstdint>
#include <math.h>

#define D_DIM   1024
#define T_DIM   50
#define STRIDEQ 10
#define NUM_POS 16
#define MAX_B   4096
#define MAX_KP  13108   /* ceil(131072/10) */
#define NWMAX   416     /* ceil(13108/32)=410, padded */

typedef unsigned long long ull;

// ---- device scratch (static; no allocations allowed) ----
__device__ ulonglong2 g_q[MAX_KP];
__device__ ulonglong2 g_a[MAX_B];
__device__ int        g_sel[MAX_B * NUM_POS];
__device__ int        g_cnt[MAX_B];
__device__ float      g_per[MAX_B];
__device__ unsigned   g_counter;

// ------------------------------------------------------------------
// Kernel 1: pack labels (strided queue rows + anchors). Warp per row.
// ------------------------------------------------------------------
__global__ void prep_labels(const int* __restrict__ xlab,
                            const int* __restrict__ qlab,
                            int B, int Kp) {
    if (blockIdx.x == 0 && threadIdx.x == 0) g_counter = 0;
    int warp = (blockIdx.x * blockDim.x + threadIdx.x) >> 5;
    int lane = threadIdx.x & 31;
    if (warp >= Kp + B) return;

    const int* lp = (warp < Kp)
        ? qlab + (long long)warp * STRIDEQ * (T_DIM * 2)
        : xlab + (long long)(warp - Kp) * (T_DIM * 2);

    int2 va = ((const int2*)lp)[lane];
    int l0b = 0, l1b = 0;
    if (32 + lane < T_DIM) {
        int2 vb = ((const int2*)lp)[32 + lane];
        l0b = vb.x; l1b = vb.y;
    }
    unsigned b0lo = __ballot_sync(0xffffffffu, va.x != 0);
    unsigned b1lo = __ballot_sync(0xffffffffu, va.y != 0);
    unsigned b0hi = __ballot_sync(0xffffffffu, l0b != 0);
    unsigned b1hi = __ballot_sync(0xffffffffu, l1b != 0);
    if (lane == 0) {
        ull v0 = (ull)b0lo | ((ull)b0hi << 32);
        ull v1 = (ull)b1lo | ((ull)b1hi << 32);
        if (warp < Kp) g_q[warp]      = make_ulonglong2(v0, v1);
        else           g_a[warp - Kp] = make_ulonglong2(v0, v1);
    }
}

// ------------------------------------------------------------------
// Kernel 2: block-per-anchor select (R10 structure = measured best).
// Single 16B load per eval; integer threshold table replaces the fp32
// compare (bit-exact by monotone construction; validated R13).
// ------------------------------------------------------------------
__global__ void __launch_bounds__(512, 4)
select_block(int B, int Kp) {
    __shared__ unsigned s_words[NWMAX];
    __shared__ int      s_T[64];
    int b    = blockIdx.x;
    int tid  = threadIdx.x;
    int w    = tid >> 5;
    int lane = tid & 31;

    float c = 1.0f / (sqrtf(2.0f) + 1e-8f);
    // T[nE] = min nc with (float)nE + (float)nc * c >= 25.0f
    if (tid < 64) {
        int nE = tid;
        int t;
        if ((float)nE >= 25.0f) t = 0;
        else {
            t = (int)((25.0f - (float)nE) / c) - 2;
            if (t < 0) t = 0;
            while ((float)nE + (float)t * c < 25.0f) t++;
        }
        s_T[tid] = t;
    }

    ulonglong2 av = g_a[b];
    ull a0 = av.x, a1 = av.y;
    ull da = a0 & a1, xa = a0 ^ a1, orA = a0 | a1;
    __syncthreads();

    int total    = 0;
    int scan_end = 0;
#pragma unroll 1
    for (int base = 0; base < Kp; base += 512) {
        int k = base + tid;
        bool pred = false;
        if (k < Kp) {
            ulonglong2 qv = g_q[k];
            ull mE = ~(qv.x ^ a0) & ~(qv.y ^ a1) & orA;
            ull mc = (da & (qv.x ^ qv.y)) | (xa & (qv.x & qv.y));
            pred = (__popcll(mc) >= s_T[__popcll(mE)]);
        }
        unsigned m = __ballot_sync(0xffffffffu, pred);
        if (lane == 0) s_words[(base >> 5) + w] = m;
        total += __syncthreads_count(pred);   // barrier + exact count
        scan_end = (base + 512 < Kp) ? base + 512 : Kp;
        if (total >= NUM_POS) break;
    }

    // ---- ordered extraction of first <=16 hits (warp 0, validated) ----
    if (w == 0) {
        int nwords = (scan_end + 31) >> 5;
        int run = 0;
        for (int g = 0; g * 32 < nwords && run < NUM_POS; g++) {
            int wi = g * 32 + lane;
            unsigned word = (wi < nwords) ? s_words[wi] : 0u;
            int my = __popc(word);
            int pre = my;
#pragma unroll
            for (int o = 1; o < 32; o <<= 1) {
                int v = __shfl_up_sync(0xffffffffu, pre, o);
                if (lane >= o) pre += v;
            }
            int gtot = __shfl_sync(0xffffffffu, pre, 31);
            int rank = run + pre - my;
            while (word && rank < NUM_POS) {
                int bit = __ffs(word) - 1;
                word &= word - 1;
                g_sel[b * NUM_POS + rank++] = wi * 32 + bit;
            }
            run += gtot;
        }
        if (lane == 0) g_cnt[b] = (total < NUM_POS) ? total : NUM_POS;
    }
}

// ------------------------------------------------------------------
// Kernel 3: per anchor, 16 gathered dots (norms fused) + loss +
// last-block deterministic mean. (512,4) -> regs<=32, occ ~94%.
// ------------------------------------------------------------------
__global__ void __launch_bounds__(512, 4)
loss_kernel(const float* __restrict__ xq, const float* __restrict__ qf,
            float* __restrict__ out, int B) {
    __shared__ float4 s_anchor4[D_DIM / 4];   // 16B aligned
    __shared__ double s_red[512];
    __shared__ float  s_ssq[256];
    __shared__ float  s_loss[NUM_POS];
    __shared__ int    s_last;

    int b    = blockIdx.x;
    int tid  = threadIdx.x;
    int w    = tid >> 5;
    int lane = tid & 31;

    if (tid >= 256) {
        int i = tid - 256;
        float4 v = ((const float4*)(xq + (long long)b * D_DIM))[i];
        s_anchor4[i] = v;
        s_ssq[i] = v.x * v.x + v.y * v.y + v.z * v.z + v.w * v.w;
    }
    __syncthreads();

    int cnt = g_cnt[b];
    float loss = 0.f;
    if (w < cnt) {
        int kp = g_sel[b * NUM_POS + w];
        const float4* pk = (const float4*)(qf + (long long)kp * STRIDEQ * D_DIM);
        const float4* pa = (const float4*)s_anchor4;
        float dot = 0.f, kss = 0.f;
#pragma unroll
        for (int i = 0; i < D_DIM / 4 / 32; i++) {
            float4 a  = pa[lane + i * 32];
            float4 kk = pk[lane + i * 32];
            dot += a.x * kk.x + a.y * kk.y + a.z * kk.z + a.w * kk.w;
            kss += kk.x * kk.x + kk.y * kk.y + kk.z * kk.z + kk.w * kk.w;
        }
#pragma unroll
        for (int o = 16; o; o >>= 1) {
            dot += __shfl_xor_sync(0xffffffffu, dot, o);
            kss += __shfl_xor_sync(0xffffffffu, kss, o);
        }
        float qss = s_ssq[lane] + s_ssq[lane + 32] + s_ssq[lane + 64]
                  + s_ssq[lane + 96] + s_ssq[lane + 128] + s_ssq[lane + 160]
                  + s_ssq[lane + 192] + s_ssq[lane + 224];
#pragma unroll
        for (int o = 16; o; o >>= 1) qss += __shfl_xor_sync(0xffffffffu, qss, o);

        float inv_q = 1.0f / (sqrtf(qss) + 1e-8f);
        float inv_k = 1.0f / (sqrtf(kss) + 1e-8f);
        float s = dot * inv_q * inv_k * 2.0f;     // / TEMPERATURE(0.5)
        float z = -s;                              // -log_sigmoid(s)
        loss = fmaxf(z, 0.f) + log1pf(expf(-fabsf(z)));
    }
    if (lane == 0 && w < NUM_POS) s_loss[w] = loss;
    __syncthreads();

    if (tid == 0) {
        float sum = 0.f;
#pragma unroll
        for (int i = 0; i < NUM_POS; i++) sum += (i < cnt) ? s_loss[i] : 0.f;
        g_per[b] = (cnt > 0) ? (sum / (float)cnt) : 0.f;
        __threadfence();
        unsigned t = atomicAdd(&g_counter, 1u);
        s_last = (t == (unsigned)(gridDim.x - 1)) ? 1 : 0;
    }
    __syncthreads();

    if (s_last) {
        double acc = 0.0;
        for (int i = tid; i < B; i += 512) acc += (double)g_per[i];
        s_red[tid] = acc;
        __syncthreads();
        for (int s = 256; s; s >>= 1) {
            if (tid < s) s_red[tid] += s_red[tid + s];
            __syncthreads();
        }
        if (tid == 0) out[0] = (float)(s_red[0] / (double)B);
    }
}

extern "C" void kernel_launch(void* const* d_in, const int* in_sizes, int n_in,
                              void* d_out, int out_size) {
    const float* xq   = (const float*)d_in[0];
    const int*   xlab = (const int*)  d_in[1];
    const float* qf   = (const float*)d_in[2];
    const int*   qlab = (const int*)  d_in[3];

    int B  = in_sizes[0] / D_DIM;                 // 4096
    int K  = in_sizes[2] / D_DIM;                 // 131072
    int Kp = (K + STRIDEQ - 1) / STRIDEQ;         // 13108

    int warps  = Kp + B;
    int blocks = (warps * 32 + 255) / 256;
    prep_labels <<<blocks, 256>>>(xlab, qlab, B, Kp);
    select_block<<<B, 512>>>(B, Kp);
    loss_kernel <<<B, 512>>>(xq, qf, (float*)d_out, B);
}

// round 16
// speedup vs baseline: 1.6684x; 1.0886x over previous
#include <cuda_runtime.h>
#include <cstdint>
#include <math.h>

#define D_DIM   1024
#define T_DIM   50
#define STRIDEQ 10
#define NUM_POS 16
#define MAX_B   4096
#define MAX_KP  13108   /* ceil(131072/10) */
#define NWMAX   416     /* ceil(13108/32)=410, padded */

typedef unsigned long long ull;

// ---- device scratch (static; no allocations allowed) ----
__device__ ulonglong2 g_q[MAX_KP];
__device__ ulonglong2 g_a[MAX_B];
__device__ int        g_sel[MAX_B * NUM_POS];
__device__ int        g_cnt[MAX_B];
__device__ float      g_per[MAX_B];
__device__ unsigned   g_counter;

// ------------------------------------------------------------------
// Kernel 1: pack labels (strided queue rows + anchors). Warp per row.
// ------------------------------------------------------------------
__global__ void prep_labels(const int* __restrict__ xlab,
                            const int* __restrict__ qlab,
                            int B, int Kp) {
    if (blockIdx.x == 0 && threadIdx.x == 0) g_counter = 0;
    int warp = (blockIdx.x * blockDim.x + threadIdx.x) >> 5;
    int lane = threadIdx.x & 31;
    if (warp >= Kp + B) return;

    const int* lp = (warp < Kp)
        ? qlab + (long long)warp * STRIDEQ * (T_DIM * 2)
        : xlab + (long long)(warp - Kp) * (T_DIM * 2);

    int2 va = ((const int2*)lp)[lane];
    int l0b = 0, l1b = 0;
    if (32 + lane < T_DIM) {
        int2 vb = ((const int2*)lp)[32 + lane];
        l0b = vb.x; l1b = vb.y;
    }
    unsigned b0lo = __ballot_sync(0xffffffffu, va.x != 0);
    unsigned b1lo = __ballot_sync(0xffffffffu, va.y != 0);
    unsigned b0hi = __ballot_sync(0xffffffffu, l0b != 0);
    unsigned b1hi = __ballot_sync(0xffffffffu, l1b != 0);
    if (lane == 0) {
        ull v0 = (ull)b0lo | ((ull)b0hi << 32);
        ull v1 = (ull)b1lo | ((ull)b1hi << 32);
        if (warp < Kp) g_q[warp]      = make_ulonglong2(v0, v1);
        else           g_a[warp - Kp] = make_ulonglong2(v0, v1);
    }
}

// ------------------------------------------------------------------
// Kernel 2: block-per-anchor select (validated best, byte-identical
// to R15: threshold table, single load, __syncthreads_count).
// ------------------------------------------------------------------
__global__ void __launch_bounds__(512, 4)
select_block(int B, int Kp) {
    __shared__ unsigned s_words[NWMAX];
    __shared__ int      s_T[64];
    int b    = blockIdx.x;
    int tid  = threadIdx.x;
    int w    = tid >> 5;
    int lane = tid & 31;

    float c = 1.0f / (sqrtf(2.0f) + 1e-8f);
    if (tid < 64) {
        int nE = tid;
        int t;
        if ((float)nE >= 25.0f) t = 0;
        else {
            t = (int)((25.0f - (float)nE) / c) - 2;
            if (t < 0) t = 0;
            while ((float)nE + (float)t * c < 25.0f) t++;
        }
        s_T[tid] = t;
    }

    ulonglong2 av = g_a[b];
    ull a0 = av.x, a1 = av.y;
    ull da = a0 & a1, xa = a0 ^ a1, orA = a0 | a1;
    __syncthreads();

    int total    = 0;
    int scan_end = 0;
#pragma unroll 1
    for (int base = 0; base < Kp; base += 512) {
        int k = base + tid;
        bool pred = false;
        if (k < Kp) {
            ulonglong2 qv = g_q[k];
            ull mE = ~(qv.x ^ a0) & ~(qv.y ^ a1) & orA;
            ull mc = (da & (qv.x ^ qv.y)) | (xa & (qv.x & qv.y));
            pred = (__popcll(mc) >= s_T[__popcll(mE)]);
        }
        unsigned m = __ballot_sync(0xffffffffu, pred);
        if (lane == 0) s_words[(base >> 5) + w] = m;
        total += __syncthreads_count(pred);
        scan_end = (base + 512 < Kp) ? base + 512 : Kp;
        if (total >= NUM_POS) break;
    }

    if (w == 0) {
        int nwords = (scan_end + 31) >> 5;
        int run = 0;
        for (int g = 0; g * 32 < nwords && run < NUM_POS; g++) {
            int wi = g * 32 + lane;
            unsigned word = (wi < nwords) ? s_words[wi] : 0u;
            int my = __popc(word);
            int pre = my;
#pragma unroll
            for (int o = 1; o < 32; o <<= 1) {
                int v = __shfl_up_sync(0xffffffffu, pre, o);
                if (lane >= o) pre += v;
            }
            int gtot = __shfl_sync(0xffffffffu, pre, 31);
            int rank = run + pre - my;
            while (word && rank < NUM_POS) {
                int bit = __ffs(word) - 1;
                word &= word - 1;
                g_sel[b * NUM_POS + rank++] = wi * 32 + bit;
            }
            run += gtot;
        }
        if (lane == 0) g_cnt[b] = (total < NUM_POS) ? total : NUM_POS;
    }
}

// ------------------------------------------------------------------
// Kernel 3: warp-per-anchor loss. Anchor row register-resident
// (8 x float4); no intra-block barriers in the dot phase. 4096 warps
// in ~1.3 waves. Last-block deterministic mean unchanged.
// ------------------------------------------------------------------
__global__ void __launch_bounds__(256)
loss_warp(const float* __restrict__ xq, const float* __restrict__ qf,
          float* __restrict__ out, int B) {
    __shared__ double s_red[256];
    __shared__ int    s_last;

    int tid  = threadIdx.x;
    int lane = tid & 31;
    int gw   = (blockIdx.x * 256 + tid) >> 5;   // global warp = anchor

    if (gw < B) {
        int b = gw;
        // ---- anchor row into registers (same lane+32i indexing) ----
        const float4* pa = (const float4*)(xq + (long long)b * D_DIM);
        float4 A[8];
#pragma unroll
        for (int i = 0; i < 8; i++) A[i] = pa[lane + i * 32];

        float qss = 0.f;
#pragma unroll
        for (int i = 0; i < 8; i++)
            qss += A[i].x * A[i].x + A[i].y * A[i].y
                 + A[i].z * A[i].z + A[i].w * A[i].w;
#pragma unroll
        for (int o = 16; o; o >>= 1) qss += __shfl_xor_sync(0xffffffffu, qss, o);
        float inv_q = 1.0f / (sqrtf(qss) + 1e-8f);

        int cnt = g_cnt[b];
        float lsum = 0.f;
#pragma unroll 1
        for (int r = 0; r < cnt; r++) {
            int kp = g_sel[b * NUM_POS + r];
            const float4* pk = (const float4*)(qf + (long long)kp * STRIDEQ * D_DIM);
            float dot = 0.f, kss = 0.f;
#pragma unroll
            for (int i = 0; i < 8; i++) {
                float4 kk = pk[lane + i * 32];
                dot += A[i].x * kk.x + A[i].y * kk.y
                     + A[i].z * kk.z + A[i].w * kk.w;
                kss += kk.x * kk.x + kk.y * kk.y + kk.z * kk.z + kk.w * kk.w;
            }
#pragma unroll
            for (int o = 16; o; o >>= 1) {
                dot += __shfl_xor_sync(0xffffffffu, dot, o);
                kss += __shfl_xor_sync(0xffffffffu, kss, o);
            }
            float inv_k = 1.0f / (sqrtf(kss) + 1e-8f);
            float s = dot * inv_q * inv_k * 2.0f;   // / TEMPERATURE(0.5)
            float z = -s;                            // -log_sigmoid(s)
            lsum += fmaxf(z, 0.f) + log1pf(expf(-fabsf(z)));
        }
        if (lane == 0)
            g_per[b] = (cnt > 0) ? (lsum / (float)cnt) : 0.f;
    }
    __syncthreads();

    if (tid == 0) {
        __threadfence();
        unsigned t = atomicAdd(&g_counter, 1u);
        s_last = (t == (unsigned)(gridDim.x - 1)) ? 1 : 0;
    }
    __syncthreads();

    // ---- last block: deterministic double-precision mean ----
    if (s_last) {
        double acc = 0.0;
        for (int i = tid; i < B; i += 256) acc += (double)g_per[i];
        s_red[tid] = acc;
        __syncthreads();
        for (int s = 128; s; s >>= 1) {
            if (tid < s) s_red[tid] += s_red[tid + s];
            __syncthreads();
        }
        if (tid == 0) out[0] = (float)(s_red[0] / (double)B);
    }
}

extern "C" void kernel_launch(void* const* d_in, const int* in_sizes, int n_in,
                              void* d_out, int out_size) {
    const float* xq   = (const float*)d_in[0];
    const int*   xlab = (const int*)  d_in[1];
    const float* qf   = (const float*)d_in[2];
    const int*   qlab = (const int*)  d_in[3];

    int B  = in_sizes[0] / D_DIM;                 // 4096
    int K  = in_sizes[2] / D_DIM;                 // 131072
    int Kp = (K + STRIDEQ - 1) / STRIDEQ;         // 13108

    int warps  = Kp + B;
    int blocks = (warps * 32 + 255) / 256;
    prep_labels <<<blocks, 256>>>(xlab, qlab, B, Kp);
    select_block<<<B, 512>>>(B, Kp);
    loss_warp   <<<(B * 32 + 255) / 256, 256>>>(xq, qf, (float*)d_out, B);
}